// round 15
// baseline (speedup 1.0000x reference)
#include <cuda_runtime.h>
#include <cuda_fp16.h>
#include <cstdint>
#include <math.h>

#define NN   20000
#define EE   320000
#define DD   128
#define HH   2
#define NB   ((NN + 1023) / 1024)

// ---------------- scratch (device globals) ------------------------------------
__device__ __align__(16) __half g_feat0[(size_t)NN * 512];
__device__ __align__(16) __half g_feat1[(size_t)NN * 512];
__device__ float g_hp[(size_t)NN * 512];        // fp32 partial (rel-0 agg)
__device__ float g_el0[NN * 2], g_er0[NN * 2];
__device__ float g_el1[NN * 2], g_er1[NN * 2];
__device__ float g_el2[NN * 2], g_er2[NN * 2];
__device__ float g_el3[NN * 2], g_er3[NN * 2];
__device__ int   g_deg0[NN], g_deg1[NN];
__device__ int   g_off0[NN + 1], g_off1[NN + 1];
__device__ int   g_pos0[NN], g_pos1[NN];
__device__ int   g_csr0[EE], g_csr1[EE];
__device__ int   g_bsum[64];
__device__ __align__(16) __half g_xh[(size_t)NN * DD];
__device__ __align__(16) __half g_h1[(size_t)NN * 256];
__device__ __align__(16) __half g_w1_0[512 * 128];
__device__ __align__(16) __half g_w1_1[512 * 128];
__device__ __align__(16) __half g_w2_0[256 * 256];
__device__ __align__(16) __half g_w2_1[256 * 256];

// ---------------- fused init ----------------------------------------------------
__global__ void init_k(const float* __restrict__ x, __half* xh,
                       float* el0, float* er0, float* el1, float* er1,
                       float* el2, float* er2, float* el3, float* er3,
                       int* deg0, int* deg1) {
    int i = blockIdx.x * blockDim.x + threadIdx.x;
    if (i < NN * DD) xh[i] = __float2half_rn(x[i]);
    if (i < NN * HH) {
        el0[i] = 0.f; er0[i] = 0.f; el1[i] = 0.f; er1[i] = 0.f;
        el2[i] = 0.f; er2[i] = 0.f; el3[i] = 0.f; er3[i] = 0.f;
    }
    if (i < NN) { deg0[i] = 0; deg1[i] = 0; }
}

// ---------------- CSR build -----------------------------------------------------
__global__ void hist_k(const int* __restrict__ dst0, const int* __restrict__ dst1,
                       int* deg0, int* deg1) {
    int i = blockIdx.x * blockDim.x + threadIdx.x;
    if (i < EE) {
        atomicAdd(&deg0[dst0[i]], 1);
        atomicAdd(&deg1[dst1[i]], 1);
    }
}
__global__ void scanA_k(const int* __restrict__ deg0, const int* __restrict__ deg1,
                        int* off0, int* off1, int* bsum) {
    const int* deg = blockIdx.y ? deg1 : deg0;
    int* off = blockIdx.y ? off1 : off0;
    int i = blockIdx.x * 1024 + threadIdx.x;
    int lane = threadIdx.x & 31, wid = threadIdx.x >> 5;
    int v = (i < NN) ? deg[i] : 0;
    int x = v;
    #pragma unroll
    for (int o = 1; o < 32; o <<= 1) {
        int t = __shfl_up_sync(0xffffffffu, x, o);
        if (lane >= o) x += t;
    }
    __shared__ int wsum[32];
    if (lane == 31) wsum[wid] = x;
    __syncthreads();
    if (wid == 0) {
        int w = wsum[lane];
        #pragma unroll
        for (int o = 1; o < 32; o <<= 1) {
            int t = __shfl_up_sync(0xffffffffu, w, o);
            if (lane >= o) w += t;
        }
        wsum[lane] = w;
    }
    __syncthreads();
    int inc = x + (wid ? wsum[wid - 1] : 0);
    if (i < NN) off[i] = inc - v;
    if (threadIdx.x == 1023) bsum[blockIdx.y * 32 + blockIdx.x] = inc;
}
__global__ void scanB_k(int* bsum, int* off0, int* off1) {
    int y = threadIdx.x >> 5, lane = threadIdx.x & 31;
    int v = (lane < NB) ? bsum[y * 32 + lane] : 0;
    int x = v;
    #pragma unroll
    for (int o = 1; o < 32; o <<= 1) {
        int t = __shfl_up_sync(0xffffffffu, x, o);
        if (lane >= o) x += t;
    }
    if (lane < NB) bsum[y * 32 + lane] = x - v;
    if (lane == NB - 1) { int* off = y ? off1 : off0; off[NN] = x; }
}
__global__ void scanC_k(const int* __restrict__ bsum, int* off0, int* off1,
                        int* pos0, int* pos1) {
    int i = blockIdx.x * 1024 + threadIdx.x;
    if (i >= NN) return;
    int y = blockIdx.y;
    int* off = y ? off1 : off0;
    int* pos = y ? pos1 : pos0;
    int val = off[i] + bsum[y * 32 + blockIdx.x];
    off[i] = val; pos[i] = val;
}
__global__ void scat_k(const int* __restrict__ src0, const int* __restrict__ dst0,
                       const int* __restrict__ src1, const int* __restrict__ dst1,
                       int* pos0, int* pos1, int* csr0, int* csr1) {
    int i = blockIdx.x * blockDim.x + threadIdx.x;
    if (i < EE) {
        csr0[atomicAdd(&pos0[dst0[i]], 1)] = src0[i];
        csr1[atomicAdd(&pos1[dst1[i]], 1)] = src1[i];
    }
}

// ---------------- merged weight transpose ---------------------------------------
__global__ void convW4_k(const float* __restrict__ Wa, const float* __restrict__ Wb,
                         const float* __restrict__ Wc, const float* __restrict__ Wd,
                         __half* da, __half* db, __half* dc, __half* dd) {
    int which = blockIdx.y;
    const float* W = which == 0 ? Wa : which == 1 ? Wb : which == 2 ? Wc : Wd;
    __half* dst     = which == 0 ? da : which == 1 ? db : which == 2 ? dc : dd;
    int K  = (which < 2) ? 128 : 256;
    int Nd = (which < 2) ? 512 : 256;
    int i = blockIdx.x * blockDim.x + threadIdx.x;
    int n = i / K, k = i % K;
    dst[i] = __float2half_rn(W[(size_t)k * Nd + n]);
}

// ---------------- mma.sync / cp.async helpers -----------------------------------
__device__ __forceinline__ uint32_t smem_u32(const void* p) {
    uint32_t a;
    asm("{ .reg .u64 t; cvta.to.shared.u64 t, %1; cvt.u32.u64 %0, t; }" : "=r"(a) : "l"(p));
    return a;
}
__device__ __forceinline__ void ldsm_x4(uint32_t* r, uint32_t addr) {
    asm volatile("ldmatrix.sync.aligned.m8n8.x4.shared.b16 {%0,%1,%2,%3}, [%4];"
                 : "=r"(r[0]), "=r"(r[1]), "=r"(r[2]), "=r"(r[3]) : "r"(addr));
}
__device__ __forceinline__ void ldsm_x2(uint32_t* r, uint32_t addr) {
    asm volatile("ldmatrix.sync.aligned.m8n8.x2.shared.b16 {%0,%1}, [%2];"
                 : "=r"(r[0]), "=r"(r[1]) : "r"(addr));
}
__device__ __forceinline__ void mma_fp16(float* d, const uint32_t* a, const uint32_t* b) {
    asm volatile(
        "mma.sync.aligned.m16n8k16.row.col.f32.f16.f16.f32 "
        "{%0,%1,%2,%3}, {%4,%5,%6,%7}, {%8,%9}, {%0,%1,%2,%3};"
        : "+f"(d[0]), "+f"(d[1]), "+f"(d[2]), "+f"(d[3])
        : "r"(a[0]), "r"(a[1]), "r"(a[2]), "r"(a[3]), "r"(b[0]), "r"(b[1]));
}
__device__ __forceinline__ void cp16(uint32_t dst, const void* src, bool valid) {
    int sz = valid ? 16 : 0;
    asm volatile("cp.async.cg.shared.global [%0], [%1], 16, %2;"
                 :: "r"(dst), "l"(src), "r"(sz));
}

// ---------------- tensor-core fp16 GEMM (single relation), cp.async ------------
#define SSTR 40
__device__ __forceinline__ void load_chunk_async(const __half* __restrict__ g,
        int ld, int rbase, int kofs, uint32_t sbase, int rlim, int tid) {
    #pragma unroll
    for (int i = 0; i < 2; i++) {
        int id = tid + i * 256;
        int r = id >> 2;
        int c = (id & 3) * 8;
        int gr = rbase + r;
        bool valid = gr < rlim;
        const __half* src = g + (size_t)(valid ? gr : 0) * ld + kofs + c;
        cp16(sbase + (uint32_t)(r * SSTR + c) * 2, src, valid);
    }
}

template<int KTOT, int O>
__global__ void __launch_bounds__(256) gemm_mma_k(
        const __half* __restrict__ A, const __half* __restrict__ B,
        __half* __restrict__ C,
        const float* __restrict__ al, const float* __restrict__ ar,
        float* __restrict__ el, float* __restrict__ er, int M, int Nd) {
    __shared__ __align__(16) __half sA[2][128 * SSTR];
    __shared__ __align__(16) __half sB[2][128 * SSTR];
    const int tid = threadIdx.x;
    const int w = tid >> 5;
    const int lane = tid & 31;
    const int rowBase = blockIdx.y * 128;
    const int colBase = blockIdx.x * 128;
    const int wRow = w >> 2;
    const int wCol = w & 3;

    uint32_t aBase[2] = { smem_u32(sA[0]), smem_u32(sA[1]) };
    uint32_t bBase[2] = { smem_u32(sB[0]), smem_u32(sB[1]) };

    float d[4][4][4];
    #pragma unroll
    for (int i = 0; i < 4; i++)
        #pragma unroll
        for (int j = 0; j < 4; j++)
            #pragma unroll
            for (int q = 0; q < 4; q++) d[i][j][q] = 0.f;

    constexpr int NKC = KTOT / 32;
    load_chunk_async(A, KTOT, rowBase, 0, aBase[0], M, tid);
    load_chunk_async(B, KTOT, colBase, 0, bBase[0], 1 << 30, tid);
    asm volatile("cp.async.commit_group;");
    asm volatile("cp.async.wait_group 0;");
    __syncthreads();

    int buf = 0;
    for (int kc = 0; kc < NKC; kc++) {
        bool more = (kc + 1) < NKC;
        if (more) {
            load_chunk_async(A, KTOT, rowBase, (kc + 1) * 32, aBase[buf ^ 1], M, tid);
            load_chunk_async(B, KTOT, colBase, (kc + 1) * 32, bBase[buf ^ 1], 1 << 30, tid);
            asm volatile("cp.async.commit_group;");
        }
        #pragma unroll
        for (int ks = 0; ks < 32; ks += 16) {
            uint32_t b[4][2];
            {
                int brow = (lane & 7);
                int bcol = ks + ((lane >> 3) & 1) * 8;
                #pragma unroll
                for (int nt = 0; nt < 4; nt++) {
                    uint32_t off = (uint32_t)(((wCol * 32 + nt * 8 + brow) * SSTR + bcol) * 2);
                    ldsm_x2(b[nt], bBase[buf] + off);
                }
            }
            int arow = (lane & 15);
            int acol = ks + (lane >> 4) * 8;
            #pragma unroll
            for (int mt = 0; mt < 4; mt++) {
                uint32_t a[4];
                uint32_t off = (uint32_t)(((wRow * 64 + mt * 16 + arow) * SSTR + acol) * 2);
                ldsm_x4(a, aBase[buf] + off);
                #pragma unroll
                for (int nt = 0; nt < 4; nt++)
                    mma_fp16(d[mt][nt], a, b[nt]);
            }
        }
        if (more) {
            asm volatile("cp.async.wait_group 0;");
            __syncthreads();
            buf ^= 1;
        }
    }

    int mlocal = lane >> 2;
    int nlocal = (lane & 3) * 2;
    float alv[4][2], arv[4][2];
    int head;
    {
        int c0 = colBase + wCol * 32 + nlocal;
        head = c0 / O;
        #pragma unroll
        for (int nt = 0; nt < 4; nt++) {
            int c = c0 + nt * 8 - head * O;
            alv[nt][0] = al[head * O + c]; alv[nt][1] = al[head * O + c + 1];
            arv[nt][0] = ar[head * O + c]; arv[nt][1] = ar[head * O + c + 1];
        }
    }
    #pragma unroll
    for (int mt = 0; mt < 4; mt++) {
        int row = rowBase + wRow * 64 + mt * 16 + mlocal;
        float pel0 = 0.f, per0 = 0.f, pel8 = 0.f, per8 = 0.f;
        #pragma unroll
        for (int nt = 0; nt < 4; nt++) {
            int col = colBase + wCol * 32 + nt * 8 + nlocal;
            if (row < M)
                *(__half2*)&C[(size_t)row * Nd + col] =
                    __floats2half2_rn(d[mt][nt][0], d[mt][nt][1]);
            if (row + 8 < M)
                *(__half2*)&C[(size_t)(row + 8) * Nd + col] =
                    __floats2half2_rn(d[mt][nt][2], d[mt][nt][3]);
            pel0 += d[mt][nt][0] * alv[nt][0] + d[mt][nt][1] * alv[nt][1];
            per0 += d[mt][nt][0] * arv[nt][0] + d[mt][nt][1] * arv[nt][1];
            pel8 += d[mt][nt][2] * alv[nt][0] + d[mt][nt][3] * alv[nt][1];
            per8 += d[mt][nt][2] * arv[nt][0] + d[mt][nt][3] * arv[nt][1];
        }
        #pragma unroll
        for (int o = 1; o < 4; o <<= 1) {
            pel0 += __shfl_xor_sync(0xffffffffu, pel0, o);
            per0 += __shfl_xor_sync(0xffffffffu, per0, o);
            pel8 += __shfl_xor_sync(0xffffffffu, pel8, o);
            per8 += __shfl_xor_sync(0xffffffffu, per8, o);
        }
        if ((lane & 3) == 0) {
            if (row < M) {
                atomicAdd(&el[row * HH + head], pel0);
                atomicAdd(&er[row * HH + head], per0);
            }
            if (row + 8 < M) {
                atomicAdd(&el[(row + 8) * HH + head], pel8);
                atomicAdd(&er[(row + 8) * HH + head], per8);
            }
        }
    }
}

// ---------------- per-relation agg: 2 warps/node, shfl-cached alphas -----------
// FINAL=0: rel-0 pass, write fp32 partial to hp.
// FINAL=1: rel-1 pass, add hp, combine heads, bias(+relu), write out.
template<int O, int FINAL>
__global__ void __launch_bounds__(256) agg_k(
        const int* __restrict__ off, const int* __restrict__ csr,
        const float* __restrict__ el, const float* __restrict__ er,
        const __half* __restrict__ feat, float* __restrict__ hp,
        const float* __restrict__ b0, const float* __restrict__ b1,
        float* __restrict__ out, __half* __restrict__ outH, int do_relu) {
    constexpr int WIDTH = 2 * O;
    constexpr int NVH = O / 32;             // halves per lane: 8 or 4
    __shared__ float s_out[4][O];
    const unsigned FULL = 0xffffffffu;
    int wid = threadIdx.x >> 5;
    int lane = threadIdx.x & 31;
    int nodeLocal = wid >> 1;
    int head = wid & 1;
    int n = blockIdx.x * 4 + nodeLocal;     // NN % 4 == 0

    int beg = off[n];
    int deg = off[n + 1] - beg;
    float ern = er[n * 2 + head];

    // phase 1: all exps (lane-strided); lane i caches edge i (first chunk)
    float dsum = 0.f;
    int sreg = 0; float ev = 0.f;
    for (int i = lane; i < deg; i += 32) {
        int s = csr[beg + i];
        float v = el[s * 2 + head] + ern;
        v = v > 0.f ? v : 0.2f * v;
        float e = __expf(v);
        dsum += e;
        if (i < 32) { sreg = s; ev = e; }
    }
    #pragma unroll
    for (int o = 16; o; o >>= 1)
        dsum += __shfl_xor_sync(FULL, dsum, o);
    float inv = 1.f / fmaxf(dsum, 1e-9f);

    float acc[NVH];
    #pragma unroll
    for (int j = 0; j < NVH; j++) acc[j] = 0.f;

    if (deg <= 32) {
        // fast path: alphas + src ids via shuffle, no reloads
        #pragma unroll 4
        for (int i = 0; i < deg; i++) {
            int s = __shfl_sync(FULL, sreg, i);
            float a = __shfl_sync(FULL, ev, i) * inv;
            const __half* fp = feat + (size_t)s * WIDTH + head * O + lane * NVH;
            if (NVH == 8) {
                uint4 r0 = *(const uint4*)fp;
                float2 f;
                f = __half22float2(*(__half2*)&r0.x); acc[0] += a * f.x; acc[1] += a * f.y;
                f = __half22float2(*(__half2*)&r0.y); acc[2] += a * f.x; acc[3] += a * f.y;
                f = __half22float2(*(__half2*)&r0.z); acc[4] += a * f.x; acc[5] += a * f.y;
                f = __half22float2(*(__half2*)&r0.w); acc[6] += a * f.x; acc[7] += a * f.y;
            } else {
                uint2 r0 = *(const uint2*)fp;
                float2 f;
                f = __half22float2(*(__half2*)&r0.x); acc[0] += a * f.x; acc[1] += a * f.y;
                f = __half22float2(*(__half2*)&r0.y); acc[2] += a * f.x; acc[3] += a * f.y;
            }
        }
    } else {
        #pragma unroll 4
        for (int i = 0; i < deg; i++) {
            int s = csr[beg + i];
            float v = el[s * 2 + head] + ern;
            v = v > 0.f ? v : 0.2f * v;
            float a = __expf(v) * inv;
            const __half* fp = feat + (size_t)s * WIDTH + head * O + lane * NVH;
            if (NVH == 8) {
                uint4 r0 = *(const uint4*)fp;
                float2 f;
                f = __half22float2(*(__half2*)&r0.x); acc[0] += a * f.x; acc[1] += a * f.y;
                f = __half22float2(*(__half2*)&r0.y); acc[2] += a * f.x; acc[3] += a * f.y;
                f = __half22float2(*(__half2*)&r0.z); acc[4] += a * f.x; acc[5] += a * f.y;
                f = __half22float2(*(__half2*)&r0.w); acc[6] += a * f.x; acc[7] += a * f.y;
            } else {
                uint2 r0 = *(const uint2*)fp;
                float2 f;
                f = __half22float2(*(__half2*)&r0.x); acc[0] += a * f.x; acc[1] += a * f.y;
                f = __half22float2(*(__half2*)&r0.y); acc[2] += a * f.x; acc[3] += a * f.y;
            }
        }
    }

    if (!FINAL) {
        float* dst = hp + (size_t)n * WIDTH + head * O + lane * NVH;
        #pragma unroll
        for (int k = 0; k < NVH; k++) dst[k] = acc[k];
    } else {
        const float* src = hp + (size_t)n * WIDTH + head * O + lane * NVH;
        #pragma unroll
        for (int k = 0; k < NVH; k++) acc[k] += src[k];
        if (head == 1) {
            #pragma unroll
            for (int k = 0; k < NVH; k++)
                s_out[nodeLocal][lane * NVH + k] = acc[k];
        }
        __syncthreads();
        if (head == 0) {
            #pragma unroll
            for (int k = 0; k < NVH; k++) {
                int j = lane * NVH + k;
                float v = acc[k] + s_out[nodeLocal][j]
                        + b0[j] + b0[j + O] + b1[j] + b1[j + O];
                v *= 0.5f;
                if (do_relu) v = fmaxf(v, 0.f);
                if (outH) outH[(size_t)n * O + j] = __float2half_rn(v);
                else      out[(size_t)n * O + j] = v;
            }
        }
    }
}

// ---------------- host launch ---------------------------------------------------
static float* symf(const void* s) { void* p = nullptr; cudaGetSymbolAddress(&p, s); return (float*)p; }
static int*   symi(const void* s) { void* p = nullptr; cudaGetSymbolAddress(&p, s); return (int*)p; }
static __half* symh(const void* s) { void* p = nullptr; cudaGetSymbolAddress(&p, s); return (__half*)p; }

struct Ctx {
    cudaStream_t s1, s2;
    cudaEvent_t fork, evInit, evW, evCSR, evG1R1, evAggB1, evG2R1;
    Ctx() {
        cudaStreamCreateWithFlags(&s1, cudaStreamNonBlocking);
        cudaStreamCreateWithFlags(&s2, cudaStreamNonBlocking);
        cudaEventCreateWithFlags(&fork,    cudaEventDisableTiming);
        cudaEventCreateWithFlags(&evInit,  cudaEventDisableTiming);
        cudaEventCreateWithFlags(&evW,     cudaEventDisableTiming);
        cudaEventCreateWithFlags(&evCSR,   cudaEventDisableTiming);
        cudaEventCreateWithFlags(&evG1R1,  cudaEventDisableTiming);
        cudaEventCreateWithFlags(&evAggB1, cudaEventDisableTiming);
        cudaEventCreateWithFlags(&evG2R1,  cudaEventDisableTiming);
    }
};

extern "C" void kernel_launch(void* const* d_in, const int* in_sizes, int n_in,
                              void* d_out, int out_size) {
    static Ctx ctx;
    const float* x     = (const float*)d_in[0];
    const int*   src0  = (const int*)d_in[1];
    const int*   dst0  = (const int*)d_in[2];
    const int*   src1  = (const int*)d_in[3];
    const int*   dst1  = (const int*)d_in[4];
    const float* W1_0  = (const float*)d_in[5];
    const float* al1_0 = (const float*)d_in[6];
    const float* ar1_0 = (const float*)d_in[7];
    const float* b1_0  = (const float*)d_in[8];
    const float* W1_1  = (const float*)d_in[9];
    const float* al1_1 = (const float*)d_in[10];
    const float* ar1_1 = (const float*)d_in[11];
    const float* b1_1  = (const float*)d_in[12];
    const float* W2_0  = (const float*)d_in[13];
    const float* al2_0 = (const float*)d_in[14];
    const float* ar2_0 = (const float*)d_in[15];
    const float* b2_0  = (const float*)d_in[16];
    const float* W2_1  = (const float*)d_in[17];
    const float* al2_1 = (const float*)d_in[18];
    const float* ar2_1 = (const float*)d_in[19];
    const float* b2_1  = (const float*)d_in[20];
    float* out = (float*)d_out;

    __half* feat0 = symh(g_feat0);
    __half* feat1 = symh(g_feat1);
    float* hp = symf(g_hp);
    float* el0 = symf(g_el0); float* er0 = symf(g_er0);
    float* el1 = symf(g_el1); float* er1 = symf(g_er1);
    float* el2 = symf(g_el2); float* er2 = symf(g_er2);
    float* el3 = symf(g_el3); float* er3 = symf(g_er3);
    int* deg0 = symi(g_deg0); int* deg1 = symi(g_deg1);
    int* off0 = symi(g_off0); int* off1 = symi(g_off1);
    int* pos0 = symi(g_pos0); int* pos1 = symi(g_pos1);
    int* csr0 = symi(g_csr0); int* csr1 = symi(g_csr1);
    int* bsum = symi(g_bsum);
    __half* xh = symh(g_xh);
    __half* h1 = symh(g_h1);
    __half* w1_0 = symh(g_w1_0); __half* w1_1 = symh(g_w1_1);
    __half* w2_0 = symh(g_w2_0); __half* w2_1 = symh(g_w2_1);

    cudaStream_t s1 = ctx.s1, s2 = ctx.s2;

    cudaEventRecord(ctx.fork, 0);
    cudaStreamWaitEvent(s1, ctx.fork, 0);
    cudaStreamWaitEvent(s2, ctx.fork, 0);

    // stream 0: fused init
    init_k<<<(NN * DD + 255) / 256, 256>>>(x, xh, el0, er0, el1, er1,
                                           el2, er2, el3, er3, deg0, deg1);
    cudaEventRecord(ctx.evInit, 0);

    // s2: weight transposes, then relation-1 layer-1 GEMM
    { dim3 g(65536 / 256, 4);
      convW4_k<<<g, 256, 0, s2>>>(W1_0, W1_1, W2_0, W2_1, w1_0, w1_1, w2_0, w2_1); }
    cudaEventRecord(ctx.evW, s2);
    cudaStreamWaitEvent(s2, ctx.evInit, 0);
    { dim3 g(4, (NN + 127) / 128);
      gemm_mma_k<128, 256><<<g, 256, 0, s2>>>(xh, w1_1, feat1,
                                              al1_1, ar1_1, el1, er1, NN, 512); }
    cudaEventRecord(ctx.evG1R1, s2);

    // s1: CSR build
    cudaStreamWaitEvent(s1, ctx.evInit, 0);
    hist_k<<<(EE + 255) / 256, 256, 0, s1>>>(dst0, dst1, deg0, deg1);
    { dim3 g(NB, 2); scanA_k<<<g, 1024, 0, s1>>>(deg0, deg1, off0, off1, bsum); }
    scanB_k<<<1, 64, 0, s1>>>(bsum, off0, off1);
    { dim3 g(NB, 2); scanC_k<<<g, 1024, 0, s1>>>(bsum, off0, off1, pos0, pos1); }
    scat_k<<<(EE + 255) / 256, 256, 0, s1>>>(src0, dst0, src1, dst1, pos0, pos1, csr0, csr1);
    cudaEventRecord(ctx.evCSR, s1);

    // stream 0: relation-0 layer-1 GEMM (needs weights)
    cudaStreamWaitEvent(0, ctx.evW, 0);
    { dim3 g(4, (NN + 127) / 128);
      gemm_mma_k<128, 256><<<g, 256>>>(xh, w1_0, feat0,
                                       al1_0, ar1_0, el0, er0, NN, 512); }

    // aggA1: rel-0 partial (overlaps gemm1_r1 on s2)
    cudaStreamWaitEvent(0, ctx.evCSR, 0);
    agg_k<256, 0><<<NN / 4, 256>>>(off0, csr0, el0, er0, feat0, hp,
                                   b1_0, b1_1, nullptr, nullptr, 0);
    // aggB1: rel-1 + combine -> h1
    cudaStreamWaitEvent(0, ctx.evG1R1, 0);
    agg_k<256, 1><<<NN / 4, 256>>>(off1, csr1, el1, er1, feat1, hp,
                                   b1_0, b1_1, nullptr, h1, 1);
    cudaEventRecord(ctx.evAggB1, 0);

    // s2: relation-1 layer-2 GEMM after h1 ready
    cudaStreamWaitEvent(s2, ctx.evAggB1, 0);
    { dim3 g(2, (NN + 127) / 128);
      gemm_mma_k<256, 128><<<g, 256, 0, s2>>>(h1, w2_1, feat1,
                                              al2_1, ar2_1, el3, er3, NN, 256); }
    cudaEventRecord(ctx.evG2R1, s2);

    // stream 0: relation-0 layer-2 GEMM + aggA2 (overlaps gemm2_r1)
    { dim3 g(2, (NN + 127) / 128);
      gemm_mma_k<256, 128><<<g, 256>>>(h1, w2_0, feat0,
                                       al2_0, ar2_0, el2, er2, NN, 256); }
    agg_k<128, 0><<<NN / 4, 256>>>(off0, csr0, el2, er2, feat0, hp,
                                   b2_0, b2_1, nullptr, nullptr, 0);
    cudaStreamWaitEvent(0, ctx.evG2R1, 0);
    agg_k<128, 1><<<NN / 4, 256>>>(off1, csr1, el3, er3, feat1, hp,
                                   b2_0, b2_1, out, nullptr, 0);
}

// round 16
// speedup vs baseline: 1.1578x; 1.1578x over previous
#include <cuda_runtime.h>
#include <cuda_fp16.h>
#include <cstdint>
#include <math.h>

#define NN   20000
#define EE   320000
#define DD   128
#define HH   2
#define NB   ((NN + 1023) / 1024)

// ---------------- scratch (device globals) ------------------------------------
__device__ __align__(16) __half g_feat0[(size_t)NN * 512];
__device__ __align__(16) __half g_feat1[(size_t)NN * 512];
__device__ float g_el0[NN * 2], g_er0[NN * 2];
__device__ float g_el1[NN * 2], g_er1[NN * 2];
__device__ float g_el2[NN * 2], g_er2[NN * 2];
__device__ float g_el3[NN * 2], g_er3[NN * 2];
__device__ int   g_deg0[NN], g_deg1[NN];
__device__ int   g_off0[NN + 1], g_off1[NN + 1];
__device__ int   g_pos0[NN], g_pos1[NN];
__device__ int   g_csr0[EE], g_csr1[EE];
__device__ int   g_bsum[64];
__device__ __align__(16) __half g_xh[(size_t)NN * DD];
__device__ __align__(16) __half g_h1[(size_t)NN * 256];
__device__ __align__(16) __half g_w1_0[512 * 128];
__device__ __align__(16) __half g_w1_1[512 * 128];
__device__ __align__(16) __half g_w2_0[256 * 256];
__device__ __align__(16) __half g_w2_1[256 * 256];

// ---------------- fused init ----------------------------------------------------
__global__ void init_k(const float* __restrict__ x, __half* xh,
                       float* el0, float* er0, float* el1, float* er1,
                       float* el2, float* er2, float* el3, float* er3,
                       int* deg0, int* deg1) {
    int i = blockIdx.x * blockDim.x + threadIdx.x;
    if (i < NN * DD) xh[i] = __float2half_rn(x[i]);
    if (i < NN * HH) {
        el0[i] = 0.f; er0[i] = 0.f; el1[i] = 0.f; er1[i] = 0.f;
        el2[i] = 0.f; er2[i] = 0.f; el3[i] = 0.f; er3[i] = 0.f;
    }
    if (i < NN) { deg0[i] = 0; deg1[i] = 0; }
}

// ---------------- CSR build -----------------------------------------------------
__global__ void hist_k(const int* __restrict__ dst0, const int* __restrict__ dst1,
                       int* deg0, int* deg1) {
    int i = blockIdx.x * blockDim.x + threadIdx.x;
    if (i < EE) {
        atomicAdd(&deg0[dst0[i]], 1);
        atomicAdd(&deg1[dst1[i]], 1);
    }
}
__global__ void scanA_k(const int* __restrict__ deg0, const int* __restrict__ deg1,
                        int* off0, int* off1, int* bsum) {
    const int* deg = blockIdx.y ? deg1 : deg0;
    int* off = blockIdx.y ? off1 : off0;
    int i = blockIdx.x * 1024 + threadIdx.x;
    int lane = threadIdx.x & 31, wid = threadIdx.x >> 5;
    int v = (i < NN) ? deg[i] : 0;
    int x = v;
    #pragma unroll
    for (int o = 1; o < 32; o <<= 1) {
        int t = __shfl_up_sync(0xffffffffu, x, o);
        if (lane >= o) x += t;
    }
    __shared__ int wsum[32];
    if (lane == 31) wsum[wid] = x;
    __syncthreads();
    if (wid == 0) {
        int w = wsum[lane];
        #pragma unroll
        for (int o = 1; o < 32; o <<= 1) {
            int t = __shfl_up_sync(0xffffffffu, w, o);
            if (lane >= o) w += t;
        }
        wsum[lane] = w;
    }
    __syncthreads();
    int inc = x + (wid ? wsum[wid - 1] : 0);
    if (i < NN) off[i] = inc - v;
    if (threadIdx.x == 1023) bsum[blockIdx.y * 32 + blockIdx.x] = inc;
}
__global__ void scanB_k(int* bsum, int* off0, int* off1) {
    int y = threadIdx.x >> 5, lane = threadIdx.x & 31;
    int v = (lane < NB) ? bsum[y * 32 + lane] : 0;
    int x = v;
    #pragma unroll
    for (int o = 1; o < 32; o <<= 1) {
        int t = __shfl_up_sync(0xffffffffu, x, o);
        if (lane >= o) x += t;
    }
    if (lane < NB) bsum[y * 32 + lane] = x - v;
    if (lane == NB - 1) { int* off = y ? off1 : off0; off[NN] = x; }
}
__global__ void scanC_k(const int* __restrict__ bsum, int* off0, int* off1,
                        int* pos0, int* pos1) {
    int i = blockIdx.x * 1024 + threadIdx.x;
    if (i >= NN) return;
    int y = blockIdx.y;
    int* off = y ? off1 : off0;
    int* pos = y ? pos1 : pos0;
    int val = off[i] + bsum[y * 32 + blockIdx.x];
    off[i] = val; pos[i] = val;
}
__global__ void scat_k(const int* __restrict__ src0, const int* __restrict__ dst0,
                       const int* __restrict__ src1, const int* __restrict__ dst1,
                       int* pos0, int* pos1, int* csr0, int* csr1) {
    int i = blockIdx.x * blockDim.x + threadIdx.x;
    if (i < EE) {
        csr0[atomicAdd(&pos0[dst0[i]], 1)] = src0[i];
        csr1[atomicAdd(&pos1[dst1[i]], 1)] = src1[i];
    }
}

// ---------------- merged weight transpose ---------------------------------------
__global__ void convW4_k(const float* __restrict__ Wa, const float* __restrict__ Wb,
                         const float* __restrict__ Wc, const float* __restrict__ Wd,
                         __half* da, __half* db, __half* dc, __half* dd) {
    int which = blockIdx.y;
    const float* W = which == 0 ? Wa : which == 1 ? Wb : which == 2 ? Wc : Wd;
    __half* dst     = which == 0 ? da : which == 1 ? db : which == 2 ? dc : dd;
    int K  = (which < 2) ? 128 : 256;
    int Nd = (which < 2) ? 512 : 256;
    int i = blockIdx.x * blockDim.x + threadIdx.x;
    int n = i / K, k = i % K;
    dst[i] = __float2half_rn(W[(size_t)k * Nd + n]);
}

// ---------------- mma.sync / cp.async helpers -----------------------------------
__device__ __forceinline__ uint32_t smem_u32(const void* p) {
    uint32_t a;
    asm("{ .reg .u64 t; cvta.to.shared.u64 t, %1; cvt.u32.u64 %0, t; }" : "=r"(a) : "l"(p));
    return a;
}
__device__ __forceinline__ void ldsm_x4(uint32_t* r, uint32_t addr) {
    asm volatile("ldmatrix.sync.aligned.m8n8.x4.shared.b16 {%0,%1,%2,%3}, [%4];"
                 : "=r"(r[0]), "=r"(r[1]), "=r"(r[2]), "=r"(r[3]) : "r"(addr));
}
__device__ __forceinline__ void ldsm_x2(uint32_t* r, uint32_t addr) {
    asm volatile("ldmatrix.sync.aligned.m8n8.x2.shared.b16 {%0,%1}, [%2];"
                 : "=r"(r[0]), "=r"(r[1]) : "r"(addr));
}
__device__ __forceinline__ void mma_fp16(float* d, const uint32_t* a, const uint32_t* b) {
    asm volatile(
        "mma.sync.aligned.m16n8k16.row.col.f32.f16.f16.f32 "
        "{%0,%1,%2,%3}, {%4,%5,%6,%7}, {%8,%9}, {%0,%1,%2,%3};"
        : "+f"(d[0]), "+f"(d[1]), "+f"(d[2]), "+f"(d[3])
        : "r"(a[0]), "r"(a[1]), "r"(a[2]), "r"(a[3]), "r"(b[0]), "r"(b[1]));
}
__device__ __forceinline__ void cp16(uint32_t dst, const void* src, bool valid) {
    int sz = valid ? 16 : 0;
    asm volatile("cp.async.cg.shared.global [%0], [%1], 16, %2;"
                 :: "r"(dst), "l"(src), "r"(sz));
}

// ---------------- tensor-core fp16 GEMM, cp.async double-buffered --------------
// blockIdx.z = relation. C = A * W^T, fp32 accum, fp16 out, fused attn epilogue.
#define SSTR 40
__device__ __forceinline__ void load_chunk_async(const __half* __restrict__ g,
        int ld, int rbase, int kofs, uint32_t sbase, int rlim, int tid) {
    #pragma unroll
    for (int i = 0; i < 2; i++) {
        int id = tid + i * 256;
        int r = id >> 2;
        int c = (id & 3) * 8;
        int gr = rbase + r;
        bool valid = gr < rlim;
        const __half* src = g + (size_t)(valid ? gr : 0) * ld + kofs + c;
        cp16(sbase + (uint32_t)(r * SSTR + c) * 2, src, valid);
    }
}

template<int KTOT, int O>
__global__ void __launch_bounds__(256) gemm_mma_k(
        const __half* __restrict__ A,
        const __half* __restrict__ W0, const __half* __restrict__ W1,
        __half* __restrict__ C0, __half* __restrict__ C1,
        const float* __restrict__ al0, const float* __restrict__ ar0,
        const float* __restrict__ al1, const float* __restrict__ ar1,
        float* __restrict__ elA, float* __restrict__ erA,
        float* __restrict__ elB, float* __restrict__ erB,
        int M, int Nd) {
    const int rel = blockIdx.z;
    const __half* B = rel ? W1 : W0;
    __half* C = rel ? C1 : C0;
    const float* al = rel ? al1 : al0;
    const float* ar = rel ? ar1 : ar0;
    float* el = rel ? elB : elA;
    float* er = rel ? erB : erA;

    __shared__ __align__(16) __half sA[2][128 * SSTR];
    __shared__ __align__(16) __half sB[2][128 * SSTR];
    const int tid = threadIdx.x;
    const int w = tid >> 5;
    const int lane = tid & 31;
    const int rowBase = blockIdx.y * 128;
    const int colBase = blockIdx.x * 128;
    const int wRow = w >> 2;
    const int wCol = w & 3;

    uint32_t aBase[2] = { smem_u32(sA[0]), smem_u32(sA[1]) };
    uint32_t bBase[2] = { smem_u32(sB[0]), smem_u32(sB[1]) };

    float d[4][4][4];
    #pragma unroll
    for (int i = 0; i < 4; i++)
        #pragma unroll
        for (int j = 0; j < 4; j++)
            #pragma unroll
            for (int q = 0; q < 4; q++) d[i][j][q] = 0.f;

    constexpr int NKC = KTOT / 32;
    load_chunk_async(A, KTOT, rowBase, 0, aBase[0], M, tid);
    load_chunk_async(B, KTOT, colBase, 0, bBase[0], 1 << 30, tid);
    asm volatile("cp.async.commit_group;");
    asm volatile("cp.async.wait_group 0;");
    __syncthreads();

    int buf = 0;
    for (int kc = 0; kc < NKC; kc++) {
        bool more = (kc + 1) < NKC;
        if (more) {
            load_chunk_async(A, KTOT, rowBase, (kc + 1) * 32, aBase[buf ^ 1], M, tid);
            load_chunk_async(B, KTOT, colBase, (kc + 1) * 32, bBase[buf ^ 1], 1 << 30, tid);
            asm volatile("cp.async.commit_group;");
        }
        #pragma unroll
        for (int ks = 0; ks < 32; ks += 16) {
            uint32_t b[4][2];
            {
                int brow = (lane & 7);
                int bcol = ks + ((lane >> 3) & 1) * 8;
                #pragma unroll
                for (int nt = 0; nt < 4; nt++) {
                    uint32_t off = (uint32_t)(((wCol * 32 + nt * 8 + brow) * SSTR + bcol) * 2);
                    ldsm_x2(b[nt], bBase[buf] + off);
                }
            }
            int arow = (lane & 15);
            int acol = ks + (lane >> 4) * 8;
            #pragma unroll
            for (int mt = 0; mt < 4; mt++) {
                uint32_t a[4];
                uint32_t off = (uint32_t)(((wRow * 64 + mt * 16 + arow) * SSTR + acol) * 2);
                ldsm_x4(a, aBase[buf] + off);
                #pragma unroll
                for (int nt = 0; nt < 4; nt++)
                    mma_fp16(d[mt][nt], a, b[nt]);
            }
        }
        if (more) {
            asm volatile("cp.async.wait_group 0;");
            __syncthreads();
            buf ^= 1;
        }
    }

    int mlocal = lane >> 2;
    int nlocal = (lane & 3) * 2;
    float alv[4][2], arv[4][2];
    int head;
    {
        int c0 = colBase + wCol * 32 + nlocal;
        head = c0 / O;
        #pragma unroll
        for (int nt = 0; nt < 4; nt++) {
            int c = c0 + nt * 8 - head * O;
            alv[nt][0] = al[head * O + c]; alv[nt][1] = al[head * O + c + 1];
            arv[nt][0] = ar[head * O + c]; arv[nt][1] = ar[head * O + c + 1];
        }
    }
    #pragma unroll
    for (int mt = 0; mt < 4; mt++) {
        int row = rowBase + wRow * 64 + mt * 16 + mlocal;
        float pel0 = 0.f, per0 = 0.f, pel8 = 0.f, per8 = 0.f;
        #pragma unroll
        for (int nt = 0; nt < 4; nt++) {
            int col = colBase + wCol * 32 + nt * 8 + nlocal;
            if (row < M)
                *(__half2*)&C[(size_t)row * Nd + col] =
                    __floats2half2_rn(d[mt][nt][0], d[mt][nt][1]);
            if (row + 8 < M)
                *(__half2*)&C[(size_t)(row + 8) * Nd + col] =
                    __floats2half2_rn(d[mt][nt][2], d[mt][nt][3]);
            pel0 += d[mt][nt][0] * alv[nt][0] + d[mt][nt][1] * alv[nt][1];
            per0 += d[mt][nt][0] * arv[nt][0] + d[mt][nt][1] * arv[nt][1];
            pel8 += d[mt][nt][2] * alv[nt][0] + d[mt][nt][3] * alv[nt][1];
            per8 += d[mt][nt][2] * arv[nt][0] + d[mt][nt][3] * arv[nt][1];
        }
        #pragma unroll
        for (int o = 1; o < 4; o <<= 1) {
            pel0 += __shfl_xor_sync(0xffffffffu, pel0, o);
            per0 += __shfl_xor_sync(0xffffffffu, per0, o);
            pel8 += __shfl_xor_sync(0xffffffffu, pel8, o);
            per8 += __shfl_xor_sync(0xffffffffu, per8, o);
        }
        if ((lane & 3) == 0) {
            if (row < M) {
                atomicAdd(&el[row * HH + head], pel0);
                atomicAdd(&er[row * HH + head], per0);
            }
            if (row + 8 < M) {
                atomicAdd(&el[(row + 8) * HH + head], pel8);
                atomicAdd(&er[(row + 8) * HH + head], per8);
            }
        }
    }
}

// ---------------- 2-warps-per-node agg, both relations, shfl-cached alphas -----
template<int O>
__global__ void __launch_bounds__(256) aggw_k(
        const int* __restrict__ off0, const int* __restrict__ csr0,
        const int* __restrict__ off1, const int* __restrict__ csr1,
        const float* __restrict__ el0, const float* __restrict__ er0,
        const float* __restrict__ el1, const float* __restrict__ er1,
        const __half* __restrict__ feat0, const __half* __restrict__ feat1,
        const float* __restrict__ b0, const float* __restrict__ b1,
        float* __restrict__ out, __half* __restrict__ outH, int do_relu) {
    constexpr int WIDTH = 2 * O;
    constexpr int NVH = O / 32;             // halves per lane: 8 (O=256) or 4 (O=128)
    __shared__ float s_out[4][O];
    const unsigned FULL = 0xffffffffu;
    int wid = threadIdx.x >> 5;
    int lane = threadIdx.x & 31;
    int nodeLocal = wid >> 1;
    int head = wid & 1;
    int n = blockIdx.x * 4 + nodeLocal;     // NN % 4 == 0

    float acc[NVH];
    #pragma unroll
    for (int j = 0; j < NVH; j++) acc[j] = 0.f;

    #pragma unroll
    for (int rel = 0; rel < 2; rel++) {
        const int* off = rel ? off1 : off0;
        const int* csr = rel ? csr1 : csr0;
        const float* el = rel ? el1 : el0;
        const float* er = rel ? er1 : er0;
        const __half* feat = rel ? feat1 : feat0;
        int beg = off[n];
        int deg = off[n + 1] - beg;
        float ern = er[n * 2 + head];
        // phase 1: exps, lane i caches edge i (first 32)
        float dsum = 0.f;
        int sreg = 0; float ev = 0.f;
        for (int i = lane; i < deg; i += 32) {
            int s = csr[beg + i];
            float v = el[s * 2 + head] + ern;
            v = v > 0.f ? v : 0.2f * v;
            float e = __expf(v);
            dsum += e;
            if (i < 32) { sreg = s; ev = e; }
        }
        #pragma unroll
        for (int o = 16; o; o >>= 1)
            dsum += __shfl_xor_sync(FULL, dsum, o);
        float inv = 1.f / fmaxf(dsum, 1e-9f);
        // phase 2: gather; alpha + src via shuffle when deg<=32
        if (deg <= 32) {
            #pragma unroll 4
            for (int i = 0; i < deg; i++) {
                int s = __shfl_sync(FULL, sreg, i);
                float a = __shfl_sync(FULL, ev, i) * inv;
                const __half* fp = feat + (size_t)s * WIDTH + head * O + lane * NVH;
                if (NVH == 8) {
                    uint4 r0 = *(const uint4*)fp;
                    float2 f;
                    f = __half22float2(*(__half2*)&r0.x); acc[0] += a * f.x; acc[1] += a * f.y;
                    f = __half22float2(*(__half2*)&r0.y); acc[2] += a * f.x; acc[3] += a * f.y;
                    f = __half22float2(*(__half2*)&r0.z); acc[4] += a * f.x; acc[5] += a * f.y;
                    f = __half22float2(*(__half2*)&r0.w); acc[6] += a * f.x; acc[7] += a * f.y;
                } else {
                    uint2 r0 = *(const uint2*)fp;
                    float2 f;
                    f = __half22float2(*(__half2*)&r0.x); acc[0] += a * f.x; acc[1] += a * f.y;
                    f = __half22float2(*(__half2*)&r0.y); acc[2] += a * f.x; acc[3] += a * f.y;
                }
            }
        } else {
            #pragma unroll 4
            for (int i = 0; i < deg; i++) {
                int s = csr[beg + i];
                float v = el[s * 2 + head] + ern;
                v = v > 0.f ? v : 0.2f * v;
                float a = __expf(v) * inv;
                const __half* fp = feat + (size_t)s * WIDTH + head * O + lane * NVH;
                if (NVH == 8) {
                    uint4 r0 = *(const uint4*)fp;
                    float2 f;
                    f = __half22float2(*(__half2*)&r0.x); acc[0] += a * f.x; acc[1] += a * f.y;
                    f = __half22float2(*(__half2*)&r0.y); acc[2] += a * f.x; acc[3] += a * f.y;
                    f = __half22float2(*(__half2*)&r0.z); acc[4] += a * f.x; acc[5] += a * f.y;
                    f = __half22float2(*(__half2*)&r0.w); acc[6] += a * f.x; acc[7] += a * f.y;
                } else {
                    uint2 r0 = *(const uint2*)fp;
                    float2 f;
                    f = __half22float2(*(__half2*)&r0.x); acc[0] += a * f.x; acc[1] += a * f.y;
                    f = __half22float2(*(__half2*)&r0.y); acc[2] += a * f.x; acc[3] += a * f.y;
                }
            }
        }
    }
    // combine heads
    if (head == 1) {
        #pragma unroll
        for (int k = 0; k < NVH; k++)
            s_out[nodeLocal][lane * NVH + k] = acc[k];
    }
    __syncthreads();
    if (head == 0) {
        #pragma unroll
        for (int k = 0; k < NVH; k++) {
            int j = lane * NVH + k;
            float v = acc[k] + s_out[nodeLocal][j]
                    + b0[j] + b0[j + O] + b1[j] + b1[j + O];
            v *= 0.5f;
            if (do_relu) v = fmaxf(v, 0.f);
            if (outH) outH[(size_t)n * O + j] = __float2half_rn(v);
            else      out[(size_t)n * O + j] = v;
        }
    }
}

// ---------------- host launch ---------------------------------------------------
static float* symf(const void* s) { void* p = nullptr; cudaGetSymbolAddress(&p, s); return (float*)p; }
static int*   symi(const void* s) { void* p = nullptr; cudaGetSymbolAddress(&p, s); return (int*)p; }
static __half* symh(const void* s) { void* p = nullptr; cudaGetSymbolAddress(&p, s); return (__half*)p; }

struct Ctx {
    cudaStream_t s1, s2;
    cudaEvent_t fork1, join1, evW;
    Ctx() {
        cudaStreamCreateWithFlags(&s1, cudaStreamNonBlocking);
        cudaStreamCreateWithFlags(&s2, cudaStreamNonBlocking);
        cudaEventCreateWithFlags(&fork1, cudaEventDisableTiming);
        cudaEventCreateWithFlags(&join1, cudaEventDisableTiming);
        cudaEventCreateWithFlags(&evW,   cudaEventDisableTiming);
    }
};

extern "C" void kernel_launch(void* const* d_in, const int* in_sizes, int n_in,
                              void* d_out, int out_size) {
    static Ctx ctx;
    const float* x     = (const float*)d_in[0];
    const int*   src0  = (const int*)d_in[1];
    const int*   dst0  = (const int*)d_in[2];
    const int*   src1  = (const int*)d_in[3];
    const int*   dst1  = (const int*)d_in[4];
    const float* W1_0  = (const float*)d_in[5];
    const float* al1_0 = (const float*)d_in[6];
    const float* ar1_0 = (const float*)d_in[7];
    const float* b1_0  = (const float*)d_in[8];
    const float* W1_1  = (const float*)d_in[9];
    const float* al1_1 = (const float*)d_in[10];
    const float* ar1_1 = (const float*)d_in[11];
    const float* b1_1  = (const float*)d_in[12];
    const float* W2_0  = (const float*)d_in[13];
    const float* al2_0 = (const float*)d_in[14];
    const float* ar2_0 = (const float*)d_in[15];
    const float* b2_0  = (const float*)d_in[16];
    const float* W2_1  = (const float*)d_in[17];
    const float* al2_1 = (const float*)d_in[18];
    const float* ar2_1 = (const float*)d_in[19];
    const float* b2_1  = (const float*)d_in[20];
    float* out = (float*)d_out;

    __half* feat0 = symh(g_feat0);
    __half* feat1 = symh(g_feat1);
    float* el0 = symf(g_el0); float* er0 = symf(g_er0);
    float* el1 = symf(g_el1); float* er1 = symf(g_er1);
    float* el2 = symf(g_el2); float* er2 = symf(g_er2);
    float* el3 = symf(g_el3); float* er3 = symf(g_er3);
    int* deg0 = symi(g_deg0); int* deg1 = symi(g_deg1);
    int* off0 = symi(g_off0); int* off1 = symi(g_off1);
    int* pos0 = symi(g_pos0); int* pos1 = symi(g_pos1);
    int* csr0 = symi(g_csr0); int* csr1 = symi(g_csr1);
    int* bsum = symi(g_bsum);
    __half* xh = symh(g_xh);
    __half* h1 = symh(g_h1);
    __half* w1_0 = symh(g_w1_0); __half* w1_1 = symh(g_w1_1);
    __half* w2_0 = symh(g_w2_0); __half* w2_1 = symh(g_w2_1);

    cudaStream_t s1 = ctx.s1, s2 = ctx.s2;

    cudaEventRecord(ctx.fork1, 0);
    cudaStreamWaitEvent(s1, ctx.fork1, 0);
    cudaStreamWaitEvent(s2, ctx.fork1, 0);

    init_k<<<(NN * DD + 255) / 256, 256>>>(x, xh, el0, er0, el1, er1,
                                           el2, er2, el3, er3, deg0, deg1);

    { dim3 g(65536 / 256, 4);
      convW4_k<<<g, 256, 0, s2>>>(W1_0, W1_1, W2_0, W2_1, w1_0, w1_1, w2_0, w2_1); }
    cudaEventRecord(ctx.evW, s2);

    cudaEventRecord(ctx.join1, 0);          // marks init_k done
    cudaStreamWaitEvent(s1, ctx.join1, 0);
    hist_k<<<(EE + 255) / 256, 256, 0, s1>>>(dst0, dst1, deg0, deg1);
    { dim3 g(NB, 2); scanA_k<<<g, 1024, 0, s1>>>(deg0, deg1, off0, off1, bsum); }
    scanB_k<<<1, 64, 0, s1>>>(bsum, off0, off1);
    { dim3 g(NB, 2); scanC_k<<<g, 1024, 0, s1>>>(bsum, off0, off1, pos0, pos1); }
    scat_k<<<(EE + 255) / 256, 256, 0, s1>>>(src0, dst0, src1, dst1, pos0, pos1, csr0, csr1);
    cudaEventRecord(ctx.join1, s1);

    cudaStreamWaitEvent(0, ctx.evW, 0);
    { dim3 g(4, (NN + 127) / 128, 2);
      gemm_mma_k<128, 256><<<g, 256>>>(xh, w1_0, w1_1, feat0, feat1,
                                       al1_0, ar1_0, al1_1, ar1_1,
                                       el0, er0, el1, er1, NN, 512); }

    cudaStreamWaitEvent(0, ctx.join1, 0);   // CSR ready

    aggw_k<256><<<NN / 4, 256>>>(off0, csr0, off1, csr1,
                            el0, er0, el1, er1,
                            feat0, feat1, b1_0, b1_1, nullptr, h1, 1);

    { dim3 g(2, (NN + 127) / 128, 2);
      gemm_mma_k<256, 128><<<g, 256>>>(h1, w2_0, w2_1, feat0, feat1,
                                       al2_0, ar2_0, al2_1, ar2_1,
                                       el2, er2, el3, er3, NN, 256); }

    aggw_k<128><<<NN / 4, 256>>>(off0, csr0, off1, csr1,
                            el2, er2, el3, er3,
                            feat0, feat1, b2_0, b2_1, out, nullptr, 0);
}

// round 17
// speedup vs baseline: 1.1691x; 1.0098x over previous
#include <cuda_runtime.h>
#include <cuda_fp16.h>
#include <cstdint>
#include <math.h>

#define NN   20000
#define EE   320000
#define DD   128
#define HH   2
#define NB   ((NN + 1023) / 1024)

// ---------------- scratch (device globals) ------------------------------------
__device__ __align__(16) __half g_feat0[(size_t)NN * 512];
__device__ __align__(16) __half g_feat1[(size_t)NN * 512];
__device__ float g_el0[NN * 2], g_er0[NN * 2];
__device__ float g_el1[NN * 2], g_er1[NN * 2];
__device__ float g_el2[NN * 2], g_er2[NN * 2];
__device__ float g_el3[NN * 2], g_er3[NN * 2];
__device__ int   g_deg0[NN], g_deg1[NN];
__device__ int   g_off0[NN + 1], g_off1[NN + 1];
__device__ int   g_pos0[NN], g_pos1[NN];
__device__ int   g_csr0[EE], g_csr1[EE];
__device__ int   g_bsum[64];
__device__ __align__(16) __half g_xh[(size_t)NN * DD];
__device__ __align__(16) __half g_h1[(size_t)NN * 256];
__device__ __align__(16) __half g_w1_0[512 * 128];
__device__ __align__(16) __half g_w1_1[512 * 128];
__device__ __align__(16) __half g_w2_0[256 * 256];
__device__ __align__(16) __half g_w2_1[256 * 256];

// ---------------- fused init ----------------------------------------------------
__global__ void init_k(const float* __restrict__ x, __half* xh,
                       float* el0, float* er0, float* el1, float* er1,
                       float* el2, float* er2, float* el3, float* er3,
                       int* deg0, int* deg1) {
    int i = blockIdx.x * blockDim.x + threadIdx.x;
    if (i < NN * DD) xh[i] = __float2half_rn(x[i]);
    if (i < NN * HH) {
        el0[i] = 0.f; er0[i] = 0.f; el1[i] = 0.f; er1[i] = 0.f;
        el2[i] = 0.f; er2[i] = 0.f; el3[i] = 0.f; er3[i] = 0.f;
    }
    if (i < NN) { deg0[i] = 0; deg1[i] = 0; }
}

// ---------------- CSR build -----------------------------------------------------
__global__ void hist_k(const int* __restrict__ dst0, const int* __restrict__ dst1,
                       int* deg0, int* deg1) {
    int i = blockIdx.x * blockDim.x + threadIdx.x;
    if (i < EE) {
        atomicAdd(&deg0[dst0[i]], 1);
        atomicAdd(&deg1[dst1[i]], 1);
    }
}
__global__ void scanA_k(const int* __restrict__ deg0, const int* __restrict__ deg1,
                        int* off0, int* off1, int* bsum) {
    const int* deg = blockIdx.y ? deg1 : deg0;
    int* off = blockIdx.y ? off1 : off0;
    int i = blockIdx.x * 1024 + threadIdx.x;
    int lane = threadIdx.x & 31, wid = threadIdx.x >> 5;
    int v = (i < NN) ? deg[i] : 0;
    int x = v;
    #pragma unroll
    for (int o = 1; o < 32; o <<= 1) {
        int t = __shfl_up_sync(0xffffffffu, x, o);
        if (lane >= o) x += t;
    }
    __shared__ int wsum[32];
    if (lane == 31) wsum[wid] = x;
    __syncthreads();
    if (wid == 0) {
        int w = wsum[lane];
        #pragma unroll
        for (int o = 1; o < 32; o <<= 1) {
            int t = __shfl_up_sync(0xffffffffu, w, o);
            if (lane >= o) w += t;
        }
        wsum[lane] = w;
    }
    __syncthreads();
    int inc = x + (wid ? wsum[wid - 1] : 0);
    if (i < NN) off[i] = inc - v;
    if (threadIdx.x == 1023) bsum[blockIdx.y * 32 + blockIdx.x] = inc;
}
__global__ void scanB_k(int* bsum, int* off0, int* off1) {
    int y = threadIdx.x >> 5, lane = threadIdx.x & 31;
    int v = (lane < NB) ? bsum[y * 32 + lane] : 0;
    int x = v;
    #pragma unroll
    for (int o = 1; o < 32; o <<= 1) {
        int t = __shfl_up_sync(0xffffffffu, x, o);
        if (lane >= o) x += t;
    }
    if (lane < NB) bsum[y * 32 + lane] = x - v;
    if (lane == NB - 1) { int* off = y ? off1 : off0; off[NN] = x; }
}
__global__ void scanC_k(const int* __restrict__ bsum, int* off0, int* off1,
                        int* pos0, int* pos1) {
    int i = blockIdx.x * 1024 + threadIdx.x;
    if (i >= NN) return;
    int y = blockIdx.y;
    int* off = y ? off1 : off0;
    int* pos = y ? pos1 : pos0;
    int val = off[i] + bsum[y * 32 + blockIdx.x];
    off[i] = val; pos[i] = val;
}
__global__ void scat_k(const int* __restrict__ src0, const int* __restrict__ dst0,
                       const int* __restrict__ src1, const int* __restrict__ dst1,
                       int* pos0, int* pos1, int* csr0, int* csr1) {
    int i = blockIdx.x * blockDim.x + threadIdx.x;
    if (i < EE) {
        csr0[atomicAdd(&pos0[dst0[i]], 1)] = src0[i];
        csr1[atomicAdd(&pos1[dst1[i]], 1)] = src1[i];
    }
}

// ---------------- merged weight transpose ---------------------------------------
__global__ void convW4_k(const float* __restrict__ Wa, const float* __restrict__ Wb,
                         const float* __restrict__ Wc, const float* __restrict__ Wd,
                         __half* da, __half* db, __half* dc, __half* dd) {
    int which = blockIdx.y;
    const float* W = which == 0 ? Wa : which == 1 ? Wb : which == 2 ? Wc : Wd;
    __half* dst     = which == 0 ? da : which == 1 ? db : which == 2 ? dc : dd;
    int K  = (which < 2) ? 128 : 256;
    int Nd = (which < 2) ? 512 : 256;
    int i = blockIdx.x * blockDim.x + threadIdx.x;
    int n = i / K, k = i % K;
    dst[i] = __float2half_rn(W[(size_t)k * Nd + n]);
}

// ---------------- mma.sync / cp.async helpers -----------------------------------
__device__ __forceinline__ uint32_t smem_u32(const void* p) {
    uint32_t a;
    asm("{ .reg .u64 t; cvta.to.shared.u64 t, %1; cvt.u32.u64 %0, t; }" : "=r"(a) : "l"(p));
    return a;
}
__device__ __forceinline__ void ldsm_x4(uint32_t* r, uint32_t addr) {
    asm volatile("ldmatrix.sync.aligned.m8n8.x4.shared.b16 {%0,%1,%2,%3}, [%4];"
                 : "=r"(r[0]), "=r"(r[1]), "=r"(r[2]), "=r"(r[3]) : "r"(addr));
}
__device__ __forceinline__ void ldsm_x2(uint32_t* r, uint32_t addr) {
    asm volatile("ldmatrix.sync.aligned.m8n8.x2.shared.b16 {%0,%1}, [%2];"
                 : "=r"(r[0]), "=r"(r[1]) : "r"(addr));
}
__device__ __forceinline__ void mma_fp16(float* d, const uint32_t* a, const uint32_t* b) {
    asm volatile(
        "mma.sync.aligned.m16n8k16.row.col.f32.f16.f16.f32 "
        "{%0,%1,%2,%3}, {%4,%5,%6,%7}, {%8,%9}, {%0,%1,%2,%3};"
        : "+f"(d[0]), "+f"(d[1]), "+f"(d[2]), "+f"(d[3])
        : "r"(a[0]), "r"(a[1]), "r"(a[2]), "r"(a[3]), "r"(b[0]), "r"(b[1]));
}
__device__ __forceinline__ void cp16(uint32_t dst, const void* src, bool valid) {
    int sz = valid ? 16 : 0;
    asm volatile("cp.async.cg.shared.global [%0], [%1], 16, %2;"
                 :: "r"(dst), "l"(src), "r"(sz));
}

// ---------------- tensor-core fp16 GEMM, 3-stage cp.async pipeline -------------
// blockIdx.z = relation. C = A * W^T, fp32 accum, fp16 out, fused attn epilogue.
#define SSTR 40
__device__ __forceinline__ void load_chunk_async(const __half* __restrict__ g,
        int ld, int rbase, int kofs, uint32_t sbase, int rlim, int tid) {
    #pragma unroll
    for (int i = 0; i < 2; i++) {
        int id = tid + i * 256;
        int r = id >> 2;
        int c = (id & 3) * 8;
        int gr = rbase + r;
        bool valid = gr < rlim;
        const __half* src = g + (size_t)(valid ? gr : 0) * ld + kofs + c;
        cp16(sbase + (uint32_t)(r * SSTR + c) * 2, src, valid);
    }
}

template<int KTOT, int O>
__global__ void __launch_bounds__(256) gemm_mma_k(
        const __half* __restrict__ A,
        const __half* __restrict__ W0, const __half* __restrict__ W1,
        __half* __restrict__ C0, __half* __restrict__ C1,
        const float* __restrict__ al0, const float* __restrict__ ar0,
        const float* __restrict__ al1, const float* __restrict__ ar1,
        float* __restrict__ elA, float* __restrict__ erA,
        float* __restrict__ elB, float* __restrict__ erB,
        int M, int Nd) {
    const int rel = blockIdx.z;
    const __half* B = rel ? W1 : W0;
    __half* C = rel ? C1 : C0;
    const float* al = rel ? al1 : al0;
    const float* ar = rel ? ar1 : ar0;
    float* el = rel ? elB : elA;
    float* er = rel ? erB : erA;

    __shared__ __align__(16) __half sA[3][128 * SSTR];
    __shared__ __align__(16) __half sB[3][128 * SSTR];
    const int tid = threadIdx.x;
    const int w = tid >> 5;
    const int lane = tid & 31;
    const int rowBase = blockIdx.y * 128;
    const int colBase = blockIdx.x * 128;
    const int wRow = w >> 2;
    const int wCol = w & 3;

    uint32_t aBase[3] = { smem_u32(sA[0]), smem_u32(sA[1]), smem_u32(sA[2]) };
    uint32_t bBase[3] = { smem_u32(sB[0]), smem_u32(sB[1]), smem_u32(sB[2]) };

    float d[4][4][4];
    #pragma unroll
    for (int i = 0; i < 4; i++)
        #pragma unroll
        for (int j = 0; j < 4; j++)
            #pragma unroll
            for (int q = 0; q < 4; q++) d[i][j][q] = 0.f;

    constexpr int NKC = KTOT / 32;
    // prologue: chunks 0,1 in flight (separate groups)
    load_chunk_async(A, KTOT, rowBase, 0, aBase[0], M, tid);
    load_chunk_async(B, KTOT, colBase, 0, bBase[0], 1 << 30, tid);
    asm volatile("cp.async.commit_group;");
    if (NKC > 1) {
        load_chunk_async(A, KTOT, rowBase, 32, aBase[1], M, tid);
        load_chunk_async(B, KTOT, colBase, 32, bBase[1], 1 << 30, tid);
        asm volatile("cp.async.commit_group;");
    }

    for (int kc = 0; kc < NKC; kc++) {
        // ensure chunk kc is resident: one younger group may stay in flight
        if (kc + 1 < NKC) asm volatile("cp.async.wait_group 1;");
        else              asm volatile("cp.async.wait_group 0;");
        __syncthreads();
        int buf = kc % 3;
        // issue chunk kc+2 into buffer (kc+2)%3 (last read at iteration kc-1)
        if (kc + 2 < NKC) {
            int nb = (kc + 2) % 3;
            load_chunk_async(A, KTOT, rowBase, (kc + 2) * 32, aBase[nb], M, tid);
            load_chunk_async(B, KTOT, colBase, (kc + 2) * 32, bBase[nb], 1 << 30, tid);
            asm volatile("cp.async.commit_group;");
        }
        #pragma unroll
        for (int ks = 0; ks < 32; ks += 16) {
            uint32_t b[4][2];
            {
                int brow = (lane & 7);
                int bcol = ks + ((lane >> 3) & 1) * 8;
                #pragma unroll
                for (int nt = 0; nt < 4; nt++) {
                    uint32_t off = (uint32_t)(((wCol * 32 + nt * 8 + brow) * SSTR + bcol) * 2);
                    ldsm_x2(b[nt], bBase[buf] + off);
                }
            }
            int arow = (lane & 15);
            int acol = ks + (lane >> 4) * 8;
            #pragma unroll
            for (int mt = 0; mt < 4; mt++) {
                uint32_t a[4];
                uint32_t off = (uint32_t)(((wRow * 64 + mt * 16 + arow) * SSTR + acol) * 2);
                ldsm_x4(a, aBase[buf] + off);
                #pragma unroll
                for (int nt = 0; nt < 4; nt++)
                    mma_fp16(d[mt][nt], a, b[nt]);
            }
        }
        __syncthreads();   // all reads of buf done before it's overwritten later
    }

    int mlocal = lane >> 2;
    int nlocal = (lane & 3) * 2;
    float alv[4][2], arv[4][2];
    int head;
    {
        int c0 = colBase + wCol * 32 + nlocal;
        head = c0 / O;
        #pragma unroll
        for (int nt = 0; nt < 4; nt++) {
            int c = c0 + nt * 8 - head * O;
            alv[nt][0] = al[head * O + c]; alv[nt][1] = al[head * O + c + 1];
            arv[nt][0] = ar[head * O + c]; arv[nt][1] = ar[head * O + c + 1];
        }
    }
    #pragma unroll
    for (int mt = 0; mt < 4; mt++) {
        int row = rowBase + wRow * 64 + mt * 16 + mlocal;
        float pel0 = 0.f, per0 = 0.f, pel8 = 0.f, per8 = 0.f;
        #pragma unroll
        for (int nt = 0; nt < 4; nt++) {
            int col = colBase + wCol * 32 + nt * 8 + nlocal;
            if (row < M)
                *(__half2*)&C[(size_t)row * Nd + col] =
                    __floats2half2_rn(d[mt][nt][0], d[mt][nt][1]);
            if (row + 8 < M)
                *(__half2*)&C[(size_t)(row + 8) * Nd + col] =
                    __floats2half2_rn(d[mt][nt][2], d[mt][nt][3]);
            pel0 += d[mt][nt][0] * alv[nt][0] + d[mt][nt][1] * alv[nt][1];
            per0 += d[mt][nt][0] * arv[nt][0] + d[mt][nt][1] * arv[nt][1];
            pel8 += d[mt][nt][2] * alv[nt][0] + d[mt][nt][3] * alv[nt][1];
            per8 += d[mt][nt][2] * arv[nt][0] + d[mt][nt][3] * arv[nt][1];
        }
        #pragma unroll
        for (int o = 1; o < 4; o <<= 1) {
            pel0 += __shfl_xor_sync(0xffffffffu, pel0, o);
            per0 += __shfl_xor_sync(0xffffffffu, per0, o);
            pel8 += __shfl_xor_sync(0xffffffffu, pel8, o);
            per8 += __shfl_xor_sync(0xffffffffu, per8, o);
        }
        if ((lane & 3) == 0) {
            if (row < M) {
                atomicAdd(&el[row * HH + head], pel0);
                atomicAdd(&er[row * HH + head], per0);
            }
            if (row + 8 < M) {
                atomicAdd(&el[(row + 8) * HH + head], pel8);
                atomicAdd(&er[(row + 8) * HH + head], per8);
            }
        }
    }
}

// ---------------- 2-warps-per-node agg, both relations, shfl-cached alphas -----
template<int O>
__global__ void __launch_bounds__(256) aggw_k(
        const int* __restrict__ off0, const int* __restrict__ csr0,
        const int* __restrict__ off1, const int* __restrict__ csr1,
        const float* __restrict__ el0, const float* __restrict__ er0,
        const float* __restrict__ el1, const float* __restrict__ er1,
        const __half* __restrict__ feat0, const __half* __restrict__ feat1,
        const float* __restrict__ b0, const float* __restrict__ b1,
        float* __restrict__ out, __half* __restrict__ outH, int do_relu) {
    constexpr int WIDTH = 2 * O;
    constexpr int NVH = O / 32;
    __shared__ float s_out[4][O];
    const unsigned FULL = 0xffffffffu;
    int wid = threadIdx.x >> 5;
    int lane = threadIdx.x & 31;
    int nodeLocal = wid >> 1;
    int head = wid & 1;
    int n = blockIdx.x * 4 + nodeLocal;

    float acc[NVH];
    #pragma unroll
    for (int j = 0; j < NVH; j++) acc[j] = 0.f;

    #pragma unroll
    for (int rel = 0; rel < 2; rel++) {
        const int* off = rel ? off1 : off0;
        const int* csr = rel ? csr1 : csr0;
        const float* el = rel ? el1 : el0;
        const float* er = rel ? er1 : er0;
        const __half* feat = rel ? feat1 : feat0;
        int beg = off[n];
        int deg = off[n + 1] - beg;
        float ern = er[n * 2 + head];
        float dsum = 0.f;
        int sreg = 0; float ev = 0.f;
        for (int i = lane; i < deg; i += 32) {
            int s = csr[beg + i];
            float v = el[s * 2 + head] + ern;
            v = v > 0.f ? v : 0.2f * v;
            float e = __expf(v);
            dsum += e;
            if (i < 32) { sreg = s; ev = e; }
        }
        #pragma unroll
        for (int o = 16; o; o >>= 1)
            dsum += __shfl_xor_sync(FULL, dsum, o);
        float inv = 1.f / fmaxf(dsum, 1e-9f);
        if (deg <= 32) {
            #pragma unroll 4
            for (int i = 0; i < deg; i++) {
                int s = __shfl_sync(FULL, sreg, i);
                float a = __shfl_sync(FULL, ev, i) * inv;
                const __half* fp = feat + (size_t)s * WIDTH + head * O + lane * NVH;
                if (NVH == 8) {
                    uint4 r0 = *(const uint4*)fp;
                    float2 f;
                    f = __half22float2(*(__half2*)&r0.x); acc[0] += a * f.x; acc[1] += a * f.y;
                    f = __half22float2(*(__half2*)&r0.y); acc[2] += a * f.x; acc[3] += a * f.y;
                    f = __half22float2(*(__half2*)&r0.z); acc[4] += a * f.x; acc[5] += a * f.y;
                    f = __half22float2(*(__half2*)&r0.w); acc[6] += a * f.x; acc[7] += a * f.y;
                } else {
                    uint2 r0 = *(const uint2*)fp;
                    float2 f;
                    f = __half22float2(*(__half2*)&r0.x); acc[0] += a * f.x; acc[1] += a * f.y;
                    f = __half22float2(*(__half2*)&r0.y); acc[2] += a * f.x; acc[3] += a * f.y;
                }
            }
        } else {
            #pragma unroll 4
            for (int i = 0; i < deg; i++) {
                int s = csr[beg + i];
                float v = el[s * 2 + head] + ern;
                v = v > 0.f ? v : 0.2f * v;
                float a = __expf(v) * inv;
                const __half* fp = feat + (size_t)s * WIDTH + head * O + lane * NVH;
                if (NVH == 8) {
                    uint4 r0 = *(const uint4*)fp;
                    float2 f;
                    f = __half22float2(*(__half2*)&r0.x); acc[0] += a * f.x; acc[1] += a * f.y;
                    f = __half22float2(*(__half2*)&r0.y); acc[2] += a * f.x; acc[3] += a * f.y;
                    f = __half22float2(*(__half2*)&r0.z); acc[4] += a * f.x; acc[5] += a * f.y;
                    f = __half22float2(*(__half2*)&r0.w); acc[6] += a * f.x; acc[7] += a * f.y;
                } else {
                    uint2 r0 = *(const uint2*)fp;
                    float2 f;
                    f = __half22float2(*(__half2*)&r0.x); acc[0] += a * f.x; acc[1] += a * f.y;
                    f = __half22float2(*(__half2*)&r0.y); acc[2] += a * f.x; acc[3] += a * f.y;
                }
            }
        }
    }
    if (head == 1) {
        #pragma unroll
        for (int k = 0; k < NVH; k++)
            s_out[nodeLocal][lane * NVH + k] = acc[k];
    }
    __syncthreads();
    if (head == 0) {
        #pragma unroll
        for (int k = 0; k < NVH; k++) {
            int j = lane * NVH + k;
            float v = acc[k] + s_out[nodeLocal][j]
                    + b0[j] + b0[j + O] + b1[j] + b1[j + O];
            v *= 0.5f;
            if (do_relu) v = fmaxf(v, 0.f);
            if (outH) outH[(size_t)n * O + j] = __float2half_rn(v);
            else      out[(size_t)n * O + j] = v;
        }
    }
}

// ---------------- host launch ---------------------------------------------------
static float* symf(const void* s) { void* p = nullptr; cudaGetSymbolAddress(&p, s); return (float*)p; }
static int*   symi(const void* s) { void* p = nullptr; cudaGetSymbolAddress(&p, s); return (int*)p; }
static __half* symh(const void* s) { void* p = nullptr; cudaGetSymbolAddress(&p, s); return (__half*)p; }

struct Ctx {
    cudaStream_t s1, s2;
    cudaEvent_t fork1, join1, evW, evInit;
    Ctx() {
        cudaStreamCreateWithFlags(&s1, cudaStreamNonBlocking);
        cudaStreamCreateWithFlags(&s2, cudaStreamNonBlocking);
        cudaEventCreateWithFlags(&fork1, cudaEventDisableTiming);
        cudaEventCreateWithFlags(&join1, cudaEventDisableTiming);
        cudaEventCreateWithFlags(&evW,   cudaEventDisableTiming);
        cudaEventCreateWithFlags(&evInit, cudaEventDisableTiming);
    }
};

extern "C" void kernel_launch(void* const* d_in, const int* in_sizes, int n_in,
                              void* d_out, int out_size) {
    static Ctx ctx;
    const float* x     = (const float*)d_in[0];
    const int*   src0  = (const int*)d_in[1];
    const int*   dst0  = (const int*)d_in[2];
    const int*   src1  = (const int*)d_in[3];
    const int*   dst1  = (const int*)d_in[4];
    const float* W1_0  = (const float*)d_in[5];
    const float* al1_0 = (const float*)d_in[6];
    const float* ar1_0 = (const float*)d_in[7];
    const float* b1_0  = (const float*)d_in[8];
    const float* W1_1  = (const float*)d_in[9];
    const float* al1_1 = (const float*)d_in[10];
    const float* ar1_1 = (const float*)d_in[11];
    const float* b1_1  = (const float*)d_in[12];
    const float* W2_0  = (const float*)d_in[13];
    const float* al2_0 = (const float*)d_in[14];
    const float* ar2_0 = (const float*)d_in[15];
    const float* b2_0  = (const float*)d_in[16];
    const float* W2_1  = (const float*)d_in[17];
    const float* al2_1 = (const float*)d_in[18];
    const float* ar2_1 = (const float*)d_in[19];
    const float* b2_1  = (const float*)d_in[20];
    float* out = (float*)d_out;

    __half* feat0 = symh(g_feat0);
    __half* feat1 = symh(g_feat1);
    float* el0 = symf(g_el0); float* er0 = symf(g_er0);
    float* el1 = symf(g_el1); float* er1 = symf(g_er1);
    float* el2 = symf(g_el2); float* er2 = symf(g_er2);
    float* el3 = symf(g_el3); float* er3 = symf(g_er3);
    int* deg0 = symi(g_deg0); int* deg1 = symi(g_deg1);
    int* off0 = symi(g_off0); int* off1 = symi(g_off1);
    int* pos0 = symi(g_pos0); int* pos1 = symi(g_pos1);
    int* csr0 = symi(g_csr0); int* csr1 = symi(g_csr1);
    int* bsum = symi(g_bsum);
    __half* xh = symh(g_xh);
    __half* h1 = symh(g_h1);
    __half* w1_0 = symh(g_w1_0); __half* w1_1 = symh(g_w1_1);
    __half* w2_0 = symh(g_w2_0); __half* w2_1 = symh(g_w2_1);

    cudaStream_t s1 = ctx.s1, s2 = ctx.s2;

    cudaEventRecord(ctx.fork1, 0);
    cudaStreamWaitEvent(s1, ctx.fork1, 0);
    cudaStreamWaitEvent(s2, ctx.fork1, 0);

    // launch #1
    init_k<<<(NN * DD + 255) / 256, 256>>>(x, xh, el0, er0, el1, er1,
                                           el2, er2, el3, er3, deg0, deg1);
    cudaEventRecord(ctx.evInit, 0);

    // launch #2
    { dim3 g(65536 / 256, 4);
      convW4_k<<<g, 256, 0, s2>>>(W1_0, W1_1, W2_0, W2_1, w1_0, w1_1, w2_0, w2_1); }
    cudaEventRecord(ctx.evW, s2);

    // launches #3..#5 (CSR part 1, on s1)
    cudaStreamWaitEvent(s1, ctx.evInit, 0);
    hist_k<<<(EE + 255) / 256, 256, 0, s1>>>(dst0, dst1, deg0, deg1);
    { dim3 g(NB, 2); scanA_k<<<g, 1024, 0, s1>>>(deg0, deg1, off0, off1, bsum); }
    scanB_k<<<1, 64, 0, s1>>>(bsum, off0, off1);

    // launch #6: layer-1 GEMM (profiled by ncu -s 5 -c 1)
    cudaStreamWaitEvent(0, ctx.evW, 0);
    { dim3 g(4, (NN + 127) / 128, 2);
      gemm_mma_k<128, 256><<<g, 256>>>(xh, w1_0, w1_1, feat0, feat1,
                                       al1_0, ar1_0, al1_1, ar1_1,
                                       el0, er0, el1, er1, NN, 512); }

    // launches #7..#8 (CSR part 2, on s1)
    { dim3 g(NB, 2); scanC_k<<<g, 1024, 0, s1>>>(bsum, off0, off1, pos0, pos1); }
    scat_k<<<(EE + 255) / 256, 256, 0, s1>>>(src0, dst0, src1, dst1, pos0, pos1, csr0, csr1);
    cudaEventRecord(ctx.join1, s1);

    cudaStreamWaitEvent(0, ctx.join1, 0);   // CSR ready

    aggw_k<256><<<NN / 4, 256>>>(off0, csr0, off1, csr1,
                            el0, er0, el1, er1,
                            feat0, feat1, b1_0, b1_1, nullptr, h1, 1);

    { dim3 g(2, (NN + 127) / 128, 2);
      gemm_mma_k<256, 128><<<g, 256>>>(h1, w2_0, w2_1, feat0, feat1,
                                       al2_0, ar2_0, al2_1, ar2_1,
                                       el2, er2, el3, er3, NN, 256); }

    aggw_k<128><<<NN / 4, 256>>>(off0, csr0, off1, csr1,
                            el2, er2, el3, er3,
                            feat0, feat1, b2_0, b2_1, out, nullptr, 0);
}